// round 5
// baseline (speedup 1.0000x reference)
#include <cuda_runtime.h>
#include <math.h>
#include <stdint.h>

// ---------------------------------------------------------------------------
// DetectionLoss (FCOS-style) on GB300 — Round 5: 3 launches, pure streams.
//  launch 1: k_pre   (zero accs; verify grid; analytic per-(b,m) assignment)
//  launch 2: k_bulk  (PURE grid-stride class-focal stream, high occupancy)
//  launch 3: k_loc   (per-location losses; last block finalizes)
// ---------------------------------------------------------------------------

#define MAX_BM 4096
#define MAX_M  64

// accumulators: 0 obj, 1 cls, 2 ctr, 3 l1, 4 giou, 5 wsum
__device__ double g_acc[8];
__device__ int    g_best[MAX_BM];
__device__ int    g_anycand[MAX_BM];
__device__ unsigned int g_done;

// ---------------- math helpers -------------------------------------------

// returns sigmoid(x); sets sp = softplus(x). 2 MUFU (exp, log);
// reciprocal on the FMA pipe (quadratic seed + 2 Newton).
__device__ __forceinline__ float sigmoid_sp(float x, float& sp) {
    float e = __expf(-fabsf(x));             // MUFU #1, e in (0,1]
    float u = 1.0f + e;                      // u in (1,2]
    float y = fmaf(fmaf(0.33333334f, u, -1.5f), u, 2.1666667f);
    y = y * fmaf(-u, y, 2.0f);
    y = y * fmaf(-u, y, 2.0f);
    sp = fmaxf(x, 0.0f) + __logf(u);         // MUFU #2
    return (x >= 0.0f) ? y : (1.0f - y);
}

__device__ __forceinline__ float focal0(float x) {
    float sp; float p = sigmoid_sp(x, sp);
    return 0.75f * sp * p * p;
}
__device__ __forceinline__ float focal1(float x) {
    float sp; float p = sigmoid_sp(x, sp);
    float q = 1.0f - p;
    return 0.25f * (sp - x) * q * q;
}

// grid coordinate, bitwise-matching reference: (i + 0.5f) / N, rn division.
__device__ __forceinline__ float gcoord(int i, float fN) {
    return __fdiv_rn((float)i + 0.5f, fN);
}

__device__ __forceinline__ float blockReduceSumF(float v) {
    __shared__ float sh[32];
    int lane = threadIdx.x & 31, wid = threadIdx.x >> 5;
#pragma unroll
    for (int o = 16; o; o >>= 1) v += __shfl_down_sync(0xffffffffu, v, o);
    if (lane == 0) sh[wid] = v;
    __syncthreads();
    int nw = (blockDim.x + 31) >> 5;
    v = (threadIdx.x < nw) ? sh[threadIdx.x] : 0.0f;
    __syncthreads();
    if (wid == 0) {
#pragma unroll
        for (int o = 16; o; o >>= 1) v += __shfl_down_sync(0xffffffffu, v, o);
    }
    return v;
}

// ---------------- kernel 1: pre (verify + assign, single block) -----------

__global__ __launch_bounds__(512) void k_pre(
    const float* __restrict__ loc,       // (L,2)
    const float* __restrict__ gt_boxes,  // (B,M,4) cx,cy,w,h
    const int* __restrict__ ghp, const int* __restrict__ gwp,
    int L, int BM)
{
    int tid = threadIdx.x;
    if (tid < 8) g_acc[tid] = 0.0;
    if (tid == 0) g_done = 0u;

    __shared__ int s_ok;
    if (tid == 0) s_ok = 1;
    __syncthreads();

    int Wg = 0, Hg = 0;
    if (gwp && ghp) { Wg = *gwp; Hg = *ghp; }
    float fW = (float)Wg, fH = (float)Hg;

    // cooperative bitwise grid verification
    int ok = 1;
    if (Wg <= 0 || Hg <= 0 || (long long)Wg * Hg != L) ok = 0;
    else {
        const float2* loc2 = reinterpret_cast<const float2*>(loc);
        for (int l = tid; l < L; l += 512) {
            float2 p = loc2[l];
            int x = l % Wg, y = l / Wg;
            if (p.x != gcoord(x, fW) || p.y != gcoord(y, fH)) { ok = 0; break; }
        }
    }
    if (!ok) atomicAnd(&s_ok, 0);
    __syncthreads();
    int gok = s_ok;

    float rx = (Wg > 0) ? 1.0f / fW : 0.0f;
    float ry = (Hg > 0) ? 1.0f / fH : 0.0f;
    if (!(gwp && ghp)) {
        Wg = (int)(sqrtf((float)L) + 0.5f); Hg = Wg;
        fW = (float)Wg; fH = (float)Hg;
        rx = 1.0f / fW; ry = 1.0f / fH;
    }

    for (int bm = tid; bm < BM; bm += 512) {
        float4 gb = reinterpret_cast<const float4*>(gt_boxes)[bm];
        float cx = gb.x, cy = gb.y, w = gb.z, h = gb.w;
        float x1 = cx - w * 0.5f, y1 = cy - h * 0.5f;
        float x2 = cx + w * 0.5f, y2 = cy + h * 0.5f;

        if (gok) {
            int W = Wg, H = Hg;
            int ilo = (int)floorf(x1 * fW - 0.5f) + 1;
            ilo = max(0, min(ilo, W));
            while (ilo > 0 && gcoord(ilo - 1, fW) > x1) ilo--;
            while (ilo < W && !(gcoord(ilo, fW) > x1)) ilo++;
            int ihi = (int)ceilf(x2 * fW - 0.5f) - 1;
            ihi = max(-1, min(ihi, W - 1));
            while (ihi < W - 1 && gcoord(ihi + 1, fW) < x2) ihi++;
            while (ihi >= 0 && !(gcoord(ihi, fW) < x2)) ihi--;
            int jlo = (int)floorf(y1 * fH - 0.5f) + 1;
            jlo = max(0, min(jlo, H));
            while (jlo > 0 && gcoord(jlo - 1, fH) > y1) jlo--;
            while (jlo < H && !(gcoord(jlo, fH) > y1)) jlo++;
            int jhi = (int)ceilf(y2 * fH - 0.5f) - 1;
            jhi = max(-1, min(jhi, H - 1));
            while (jhi < H - 1 && gcoord(jhi + 1, fH) < y2) jhi++;
            while (jhi >= 0 && !(gcoord(jhi, fH) < y2)) jhi--;

            bool anyin = (ilo <= ihi) && (jlo <= jhi);

            int icg = (int)floorf(cx * fW - 0.5f);
            int jcg = (int)floorf(cy * fH - 0.5f);
            bool anyx = false, anyy = false;
            if (anyin) {
                for (int i = max(ilo, icg - 3); i <= min(ihi, icg + 3); i++)
                    anyx |= (fabsf(gcoord(i, fW) - cx) <= rx);
                for (int j = max(jlo, jcg - 3); j <= min(jhi, jcg + 3); j++)
                    anyy |= (fabsf(gcoord(j, fH) - cy) <= ry);
            }
            bool anyc = anyin && anyx && anyy;

            int ailo, aihi, ajlo, ajhi;
            if (anyin) { ailo = ilo; aihi = ihi; ajlo = jlo; ajhi = jhi; }
            else       { ailo = 0;   aihi = Wg-1; ajlo = 0;  ajhi = Hg-1; }
            int ic = max(ailo, min(icg, aihi));
            int jc = max(ajlo, min(jcg, ajhi));
            int ii0 = max(ailo, ic - 2), ii1 = min(aihi, ic + 2);
            int jj0 = max(ajlo, jc - 2), jj1 = min(ajhi, jc + 2);
            unsigned long long bk = ~0ull;
            for (int j = jj0; j <= jj1; j++) {
                float dy = gcoord(j, fH) - cy;
                float dy2 = __fmul_rn(dy, dy);
                for (int i = ii0; i <= ii1; i++) {
                    float dx = gcoord(i, fW) - cx;
                    float dist = __fadd_rn(__fmul_rn(dx, dx), dy2);
                    unsigned long long key =
                        ((unsigned long long)__float_as_uint(dist) << 32) |
                        (unsigned int)(j * Wg + i);
                    bk = min(bk, key);
                }
            }
            g_anycand[bm] = anyc ? 1 : 0;
            g_best[bm]    = (int)(bk & 0xffffffffu);
        } else {
            // generic fallback: serial scan (correct; only on unexpected input)
            bool anyc = false, anyin = false;
            float bd_in = 3.0e38f;  int bi_in = 0;
            float bd_all = 3.0e38f; int bi_all = 0;
            const float2* loc2 = reinterpret_cast<const float2*>(loc);
            for (int l = 0; l < L; l++) {
                float2 p = loc2[l];
                float lx = p.x, ly = p.y;
                bool inb = (lx > x1) && (ly > y1) && (lx < x2) && (ly < y2);
                float dx = lx - cx, dy = ly - cy;
                float dist = __fadd_rn(__fmul_rn(dx, dx), __fmul_rn(dy, dy));
                bool inc = (fabsf(dx) <= rx) && (fabsf(dy) <= ry);
                anyc  |= (inb && inc);
                anyin |= inb;
                if (dist < bd_all) { bd_all = dist; bi_all = l; }
                if (inb && dist < bd_in) { bd_in = dist; bi_in = l; }
            }
            g_anycand[bm] = anyc ? 1 : 0;
            g_best[bm]    = anyin ? bi_in : bi_all;
        }
    }
}

// ---------------- kernel 2: PURE bulk class-focal stream -------------------

__global__ __launch_bounds__(256) void k_bulk(
    const float* __restrict__ logits, long long total)
{
    long long n4 = total >> 2;
    const float4* lg4 = reinterpret_cast<const float4*>(logits);
    float acc = 0.0f;
    long long stride = (long long)gridDim.x * 256;
    long long i = (long long)blockIdx.x * 256 + threadIdx.x;
#pragma unroll 4
    for (; i < n4; i += stride) {
        float4 v = lg4[i];
        acc += focal0(v.x) + focal0(v.y) + focal0(v.z) + focal0(v.w);
    }
    if (blockIdx.x == 0 && threadIdx.x == 0) {
        for (long long k = n4 << 2; k < total; k++) acc += focal0(logits[k]);
    }
    float r = blockReduceSumF(acc);
    if (threadIdx.x == 0) atomicAdd(&g_acc[1], (double)r);
}

// ---------------- kernel 3: per-location losses + finalize -----------------

__global__ __launch_bounds__(256) void k_loc(
    const float* __restrict__ boxes,     // (B,L,4)
    const float* __restrict__ deltas,    // (B,L,4)
    const float* __restrict__ logits,    // (B,L,C)
    const float* __restrict__ objn,      // (B,L)
    const float* __restrict__ ctrn,      // (B,L)
    const float* __restrict__ loc,       // (L,2)
    const float* __restrict__ gt_boxes,  // (B,M,4)
    const int*   __restrict__ gt_labels, // (B,M)
    const int* __restrict__ ghp, const int* __restrict__ gwp,
    int B, int M, int L, int C, float* __restrict__ out)
{
    int b = blockIdx.y;
    int l = blockIdx.x * 256 + threadIdx.x;

    __shared__ float sx1[MAX_M], sy1[MAX_M], sx2[MAX_M], sy2[MAX_M];
    __shared__ float scx[MAX_M], scy[MAX_M], sarea[MAX_M];
    __shared__ int   slab[MAX_M], sbest[MAX_M], sany[MAX_M];

    if (threadIdx.x < M) {
        int m = threadIdx.x;
        float4 gb = reinterpret_cast<const float4*>(gt_boxes)[b * M + m];
        float cx = gb.x, cy = gb.y, w = gb.z, h = gb.w;
        sx1[m] = cx - w * 0.5f;  sy1[m] = cy - h * 0.5f;
        sx2[m] = cx + w * 0.5f;  sy2[m] = cy + h * 0.5f;
        scx[m] = cx; scy[m] = cy;
        sarea[m] = w * h;
        slab[m]  = gt_labels[b * M + m];
        sbest[m] = g_best[b * M + m];
        sany[m]  = g_anycand[b * M + m];
    }
    __syncthreads();

    float gw = gwp ? (float)(*gwp) : sqrtf((float)L);
    float gh = ghp ? (float)(*ghp) : sqrtf((float)L);
    float rx = 1.0f / gw, ry = 1.0f / gh;

    float t_obj = 0.f, t_cls = 0.f, t_ctr = 0.f, t_l1 = 0.f, t_giou = 0.f, t_w = 0.f;

    if (l < L) {
        float2 p2 = reinterpret_cast<const float2*>(loc)[l];
        float lx = p2.x, ly = p2.y;

        int   am = -1;
        float barea = 3.0e38f;
#pragma unroll 8
        for (int m = 0; m < M; m++) {
            bool inb = (lx > sx1[m]) && (ly > sy1[m]) && (lx < sx2[m]) && (ly < sy2[m]);
            bool inc = (fabsf(lx - scx[m]) <= rx) && (fabsf(ly - scy[m]) <= ry);
            bool cand = inb && inc;
            bool eff = sany[m] ? cand : (l == sbest[m]);
            if (eff && sarea[m] < barea) { barea = sarea[m]; am = m; }
        }

        int bl = b * L + l;
        float ox = objn[bl];

        if (am >= 0) {
            t_obj = focal1(ox);

            float ax1 = sx1[am], ay1 = sy1[am], ax2 = sx2[am], ay2 = sy2[am];
            float lt = fmaxf(lx - ax1, 1e-6f), tt = fmaxf(ly - ay1, 1e-6f);
            float rt = fmaxf(ax2 - lx, 1e-6f), bt = fmaxf(ay2 - ly, 1e-6f);

            float hor = __fdividef(fminf(lt, rt), fmaxf(fmaxf(lt, rt), 1e-6f));
            float ver = __fdividef(fminf(tt, bt), fmaxf(fmaxf(tt, bt), 1e-6f));
            float ctr_t = sqrtf(fmaxf(hor * ver, 0.0f));
            float wgt = fmaxf(ctr_t, 0.1f);
            t_w = wgt;

            float cxv = ctrn[bl];
            float spc; (void)sigmoid_sp(cxv, spc);
            t_ctr = (spc - cxv * ctr_t) * wgt;

            float4 bd = reinterpret_cast<const float4*>(deltas)[bl];
            float d0 = fabsf(bd.x - lt), d1 = fabsf(bd.y - tt);
            float d2 = fabsf(bd.z - rt), d3 = fabsf(bd.w - bt);
            float s0 = (d0 < 0.1f) ? 5.0f * d0 * d0 : d0 - 0.05f;
            float s1 = (d1 < 0.1f) ? 5.0f * d1 * d1 : d1 - 0.05f;
            float s2 = (d2 < 0.1f) ? 5.0f * d2 * d2 : d2 - 0.05f;
            float s3 = (d3 < 0.1f) ? 5.0f * d3 * d3 : d3 - 0.05f;
            t_l1 = 0.25f * (s0 + s1 + s2 + s3) * wgt;

            float4 pb = reinterpret_cast<const float4*>(boxes)[bl];
            float px1 = pb.x, py1 = pb.y, px2 = pb.z, py2 = pb.w;
            float ix1 = fmaxf(px1, ax1), iy1 = fmaxf(py1, ay1);
            float ix2 = fminf(px2, ax2), iy2 = fminf(py2, ay2);
            float inter = fmaxf(ix2 - ix1, 0.0f) * fmaxf(iy2 - iy1, 0.0f);
            float ap = fmaxf(px2 - px1, 0.0f) * fmaxf(py2 - py1, 0.0f);
            float ag = fmaxf(ax2 - ax1, 0.0f) * fmaxf(ay2 - ay1, 0.0f);
            float uni = ap + ag - inter;
            float iou = __fdividef(inter, fmaxf(uni, 1e-6f));
            float hx1 = fminf(px1, ax1), hy1 = fminf(py1, ay1);
            float hx2 = fmaxf(px2, ax2), hy2 = fmaxf(py2, ay2);
            float hull = fmaxf(hx2 - hx1, 0.0f) * fmaxf(hy2 - hy1, 0.0f);
            float giou = iou - __fdividef(hull - uni, fmaxf(hull, 1e-6f));
            t_giou = (1.0f - giou) * wgt;

            float xl = logits[(size_t)bl * C + slab[am]];
            t_cls = focal1(xl) - focal0(xl);
        } else {
            t_obj = focal0(ox);
        }
    }

    // ---- combined block reduction (one __syncthreads round) --------------
    {
        __shared__ float sh[6][8];
        int lane = threadIdx.x & 31, wid = threadIdx.x >> 5;
        float v0 = t_obj, v1 = t_cls, v2 = t_ctr, v3 = t_l1, v4 = t_giou, v5 = t_w;
#pragma unroll
        for (int o = 16; o; o >>= 1) {
            v0 += __shfl_down_sync(0xffffffffu, v0, o);
            v1 += __shfl_down_sync(0xffffffffu, v1, o);
            v2 += __shfl_down_sync(0xffffffffu, v2, o);
            v3 += __shfl_down_sync(0xffffffffu, v3, o);
            v4 += __shfl_down_sync(0xffffffffu, v4, o);
            v5 += __shfl_down_sync(0xffffffffu, v5, o);
        }
        if (lane == 0) {
            sh[0][wid] = v0; sh[1][wid] = v1; sh[2][wid] = v2;
            sh[3][wid] = v3; sh[4][wid] = v4; sh[5][wid] = v5;
        }
        __syncthreads();
        if (wid == 0 && lane < 6) {
            float s = 0.0f;
#pragma unroll
            for (int k = 0; k < 8; k++) s += sh[lane][k];
            atomicAdd(&g_acc[lane], (double)s);
        }
    }

    // ---- last block finalizes (k_bulk already complete by stream order) ---
    if (threadIdx.x == 0) {
        __threadfence();
        unsigned int total = gridDim.x * gridDim.y;
        unsigned int prev = atomicAdd(&g_done, 1u);
        if (prev == total - 1) {
            double nBL  = (double)B * (double)L;
            double nBLC = nBL * (double)C;
            double wsum = g_acc[5];
            double inv_w = (wsum != 0.0) ? (1.0 / wsum) : 0.0;
            double loss = 1.0 * g_acc[0] / nBL
                        + 1.5 * g_acc[1] / nBLC
                        + 0.5 * g_acc[2] * inv_w
                        + 5.0 * g_acc[3] * inv_w
                        + 2.0 * g_acc[4] * inv_w;
            out[0] = (float)loss;
        }
    }
}

// ---------------- launch ---------------------------------------------------

extern "C" void kernel_launch(void* const* d_in, const int* in_sizes, int n_in,
                              void* d_out, int out_size)
{
    const float* boxes  = (const float*)d_in[0];
    const float* deltas = (const float*)d_in[1];
    const float* logits = (const float*)d_in[2];
    const float* objn   = (const float*)d_in[3];
    const float* ctrn   = (const float*)d_in[4];
    const float* loc    = (const float*)d_in[5];
    const float* gtb    = (const float*)d_in[6];
    const int*   gtl    = (const int*)d_in[7];
    const int*   ghp    = (n_in > 8) ? (const int*)d_in[8] : nullptr;
    const int*   gwp    = (n_in > 9) ? (const int*)d_in[9] : nullptr;

    int L = in_sizes[5] / 2;
    int B = in_sizes[3] / L;
    int M = in_sizes[7] / B;
    int C = in_sizes[2] / in_sizes[3];
    int BM = B * M;

    k_pre<<<1, 512>>>(loc, gtb, ghp, gwp, L, BM);
    k_bulk<<<1184, 256>>>(logits, (long long)in_sizes[2]);
    dim3 gloc((L + 255) / 256, B);
    k_loc<<<gloc, 256>>>(boxes, deltas, logits, objn, ctrn, loc, gtb, gtl,
                         ghp, gwp, B, M, L, C, (float*)d_out);
}

// round 6
// speedup vs baseline: 1.1891x; 1.1891x over previous
#include <cuda_runtime.h>
#include <math.h>
#include <stdint.h>

// ---------------------------------------------------------------------------
// DetectionLoss (FCOS-style) on GB300 — Round 6: 2 launches, all-parallel.
//  launch 1: k_bulk (pure class-focal stream; first blocks also verify grid)
//  launch 2: k_loc  (inline analytic assignment; losses; finalize + reset)
// Globals are zero at module load; the finalizer restores that state each
// replay, so the graph is replay-deterministic with no init kernel.
// ---------------------------------------------------------------------------

#define MAX_M 64

// accumulators: 0 obj, 1 cls, 2 ctr, 3 l1, 4 giou, 5 wsum
__device__ double g_acc[8];
__device__ unsigned int g_done;     // = 0
__device__ int g_ok = 1;            // grid-verified flag

// ---------------- math helpers -------------------------------------------

// returns sigmoid(x); sets sp = softplus(x). 2 MUFU (exp, log);
// reciprocal on the FMA pipe (quadratic seed + 2 Newton).
__device__ __forceinline__ float sigmoid_sp(float x, float& sp) {
    float e = __expf(-fabsf(x));             // MUFU #1, e in (0,1]
    float u = 1.0f + e;                      // u in (1,2]
    float y = fmaf(fmaf(0.33333334f, u, -1.5f), u, 2.1666667f);
    y = y * fmaf(-u, y, 2.0f);
    y = y * fmaf(-u, y, 2.0f);
    sp = fmaxf(x, 0.0f) + __logf(u);         // MUFU #2
    return (x >= 0.0f) ? y : (1.0f - y);
}

__device__ __forceinline__ float focal0(float x) {
    float sp; float p = sigmoid_sp(x, sp);
    return 0.75f * sp * p * p;
}
__device__ __forceinline__ float focal1(float x) {
    float sp; float p = sigmoid_sp(x, sp);
    float q = 1.0f - p;
    return 0.25f * (sp - x) * q * q;
}

// grid coordinate, bitwise-matching reference: (i + 0.5f) / N, rn division.
__device__ __forceinline__ float gcoord(int i, float fN) {
    return __fdiv_rn((float)i + 0.5f, fN);
}

__device__ __forceinline__ float blockReduceSumF(float v) {
    __shared__ float sh[32];
    int lane = threadIdx.x & 31, wid = threadIdx.x >> 5;
#pragma unroll
    for (int o = 16; o; o >>= 1) v += __shfl_down_sync(0xffffffffu, v, o);
    if (lane == 0) sh[wid] = v;
    __syncthreads();
    int nw = (blockDim.x + 31) >> 5;
    v = (threadIdx.x < nw) ? sh[threadIdx.x] : 0.0f;
    __syncthreads();
    if (wid == 0) {
#pragma unroll
        for (int o = 16; o; o >>= 1) v += __shfl_down_sync(0xffffffffu, v, o);
    }
    return v;
}

// ---------------- kernel 1: bulk class-focal stream (+ grid verify) --------

__global__ __launch_bounds__(256) void k_bulk(
    const float* __restrict__ logits, long long total,
    const float* __restrict__ loc,
    const int* __restrict__ ghp, const int* __restrict__ gwp, int L)
{
    // --- lightweight grid verification by the first ceil(L/256) blocks ----
    {
        int l = blockIdx.x * 256 + threadIdx.x;
        if (l < L && blockIdx.x * 256 < L) {
            int bad = 0;
            if (ghp == nullptr || gwp == nullptr) bad = 1;
            else {
                int W = *gwp, H = *ghp;
                if (W <= 0 || H <= 0 || (long long)W * H != L) bad = 1;
                else {
                    float2 p = reinterpret_cast<const float2*>(loc)[l];
                    int x = l % W, y = l / W;
                    if (p.x != gcoord(x, (float)W) ||
                        p.y != gcoord(y, (float)H)) bad = 1;
                }
            }
            if (__any_sync(__activemask(), bad)) {
                if ((threadIdx.x & 31) == 0) atomicAnd(&g_ok, 0);
            }
        }
    }

    // --- pure grid-stride logit stream ------------------------------------
    long long n4 = total >> 2;
    const float4* lg4 = reinterpret_cast<const float4*>(logits);
    float acc = 0.0f;
    long long stride = (long long)gridDim.x * 256;
    long long i = (long long)blockIdx.x * 256 + threadIdx.x;
#pragma unroll 4
    for (; i < n4; i += stride) {
        float4 v = lg4[i];
        acc += focal0(v.x) + focal0(v.y) + focal0(v.z) + focal0(v.w);
    }
    if (blockIdx.x == 0 && threadIdx.x == 0) {
        for (long long k = n4 << 2; k < total; k++) acc += focal0(logits[k]);
    }
    float r = blockReduceSumF(acc);
    if (threadIdx.x == 0) atomicAdd(&g_acc[1], (double)r);
}

// ---------------- per-(b,m) analytic assignment (inline helper) ------------

__device__ void assign_bm(
    float cx, float cy, float x1, float y1, float x2, float y2,
    int Wg, int Hg, float fW, float fH, float rx, float ry,
    int& out_any, int& out_best)
{
    int W = Wg, H = Hg;
    int ilo = (int)floorf(x1 * fW - 0.5f) + 1;
    ilo = max(0, min(ilo, W));
    while (ilo > 0 && gcoord(ilo - 1, fW) > x1) ilo--;
    while (ilo < W && !(gcoord(ilo, fW) > x1)) ilo++;
    int ihi = (int)ceilf(x2 * fW - 0.5f) - 1;
    ihi = max(-1, min(ihi, W - 1));
    while (ihi < W - 1 && gcoord(ihi + 1, fW) < x2) ihi++;
    while (ihi >= 0 && !(gcoord(ihi, fW) < x2)) ihi--;
    int jlo = (int)floorf(y1 * fH - 0.5f) + 1;
    jlo = max(0, min(jlo, H));
    while (jlo > 0 && gcoord(jlo - 1, fH) > y1) jlo--;
    while (jlo < H && !(gcoord(jlo, fH) > y1)) jlo++;
    int jhi = (int)ceilf(y2 * fH - 0.5f) - 1;
    jhi = max(-1, min(jhi, H - 1));
    while (jhi < H - 1 && gcoord(jhi + 1, fH) < y2) jhi++;
    while (jhi >= 0 && !(gcoord(jhi, fH) < y2)) jhi--;

    bool anyin = (ilo <= ihi) && (jlo <= jhi);

    int icg = (int)floorf(cx * fW - 0.5f);
    int jcg = (int)floorf(cy * fH - 0.5f);
    bool anyx = false, anyy = false;
    if (anyin) {
        for (int i = max(ilo, icg - 3); i <= min(ihi, icg + 3); i++)
            anyx |= (fabsf(gcoord(i, fW) - cx) <= rx);
        for (int j = max(jlo, jcg - 3); j <= min(jhi, jcg + 3); j++)
            anyy |= (fabsf(gcoord(j, fH) - cy) <= ry);
    }
    bool anyc = anyin && anyx && anyy;

    int ailo, aihi, ajlo, ajhi;
    if (anyin) { ailo = ilo; aihi = ihi; ajlo = jlo; ajhi = jhi; }
    else       { ailo = 0;   aihi = W-1; ajlo = 0;   ajhi = H-1; }
    int ic = max(ailo, min(icg, aihi));
    int jc = max(ajlo, min(jcg, ajhi));
    int ii0 = max(ailo, ic - 2), ii1 = min(aihi, ic + 2);
    int jj0 = max(ajlo, jc - 2), jj1 = min(ajhi, jc + 2);
    unsigned long long bk = ~0ull;
    for (int j = jj0; j <= jj1; j++) {
        float dy = gcoord(j, fH) - cy;
        float dy2 = __fmul_rn(dy, dy);
        for (int i = ii0; i <= ii1; i++) {
            float dx = gcoord(i, fW) - cx;
            float dist = __fadd_rn(__fmul_rn(dx, dx), dy2);
            unsigned long long key =
                ((unsigned long long)__float_as_uint(dist) << 32) |
                (unsigned int)(j * W + i);
            bk = min(bk, key);
        }
    }
    out_any  = anyc ? 1 : 0;
    out_best = (int)(bk & 0xffffffffu);
}

// ---------------- kernel 2: per-location losses + finalize -----------------

__global__ __launch_bounds__(256) void k_loc(
    const float* __restrict__ boxes,     // (B,L,4)
    const float* __restrict__ deltas,    // (B,L,4)
    const float* __restrict__ logits,    // (B,L,C)
    const float* __restrict__ objn,      // (B,L)
    const float* __restrict__ ctrn,      // (B,L)
    const float* __restrict__ loc,       // (L,2)
    const float* __restrict__ gt_boxes,  // (B,M,4)
    const int*   __restrict__ gt_labels, // (B,M)
    const int* __restrict__ ghp, const int* __restrict__ gwp,
    int B, int M, int L, int C, float* __restrict__ out)
{
    int b = blockIdx.y;
    int l = blockIdx.x * 256 + threadIdx.x;

    __shared__ float sx1[MAX_M], sy1[MAX_M], sx2[MAX_M], sy2[MAX_M];
    __shared__ float scx[MAX_M], scy[MAX_M], sarea[MAX_M];
    __shared__ int   slab[MAX_M], sbest[MAX_M], sany[MAX_M];

    int Wg, Hg;
    if (gwp && ghp) { Wg = *gwp; Hg = *ghp; }
    else { Wg = (int)(sqrtf((float)L) + 0.5f); Hg = Wg; }
    float fW = (float)Wg, fH = (float)Hg;
    float rx = 1.0f / fW, ry = 1.0f / fH;

    if (threadIdx.x < M) {
        int m = threadIdx.x;
        float4 gb = reinterpret_cast<const float4*>(gt_boxes)[b * M + m];
        float cx = gb.x, cy = gb.y, w = gb.z, h = gb.w;
        float x1 = cx - w * 0.5f, y1 = cy - h * 0.5f;
        float x2 = cx + w * 0.5f, y2 = cy + h * 0.5f;
        sx1[m] = x1;  sy1[m] = y1;  sx2[m] = x2;  sy2[m] = y2;
        scx[m] = cx;  scy[m] = cy;  sarea[m] = w * h;
        slab[m] = gt_labels[b * M + m];

        int a, bs;
        if (g_ok) {
            assign_bm(cx, cy, x1, y1, x2, y2, Wg, Hg, fW, fH, rx, ry, a, bs);
        } else {
            // generic fallback: serial scan (correct; only on unexpected input)
            bool anyc = false, anyin = false;
            float bd_in = 3.0e38f;  int bi_in = 0;
            float bd_all = 3.0e38f; int bi_all = 0;
            const float2* loc2 = reinterpret_cast<const float2*>(loc);
            for (int ll = 0; ll < L; ll++) {
                float2 p = loc2[ll];
                float lx = p.x, ly = p.y;
                bool inb = (lx > x1) && (ly > y1) && (lx < x2) && (ly < y2);
                float dx = lx - cx, dy = ly - cy;
                float dist = __fadd_rn(__fmul_rn(dx, dx), __fmul_rn(dy, dy));
                bool inc = (fabsf(dx) <= rx) && (fabsf(dy) <= ry);
                anyc  |= (inb && inc);
                anyin |= inb;
                if (dist < bd_all) { bd_all = dist; bi_all = ll; }
                if (inb && dist < bd_in) { bd_in = dist; bi_in = ll; }
            }
            a = anyc ? 1 : 0;
            bs = anyin ? bi_in : bi_all;
        }
        sany[m] = a;  sbest[m] = bs;
    }
    __syncthreads();

    float t_obj = 0.f, t_cls = 0.f, t_ctr = 0.f, t_l1 = 0.f, t_giou = 0.f, t_w = 0.f;

    if (l < L) {
        float2 p2 = reinterpret_cast<const float2*>(loc)[l];
        float lx = p2.x, ly = p2.y;

        int   am = -1;
        float barea = 3.0e38f;
#pragma unroll 8
        for (int m = 0; m < M; m++) {
            bool inb = (lx > sx1[m]) && (ly > sy1[m]) && (lx < sx2[m]) && (ly < sy2[m]);
            bool inc = (fabsf(lx - scx[m]) <= rx) && (fabsf(ly - scy[m]) <= ry);
            bool cand = inb && inc;
            bool eff = sany[m] ? cand : (l == sbest[m]);
            if (eff && sarea[m] < barea) { barea = sarea[m]; am = m; }
        }

        int bl = b * L + l;
        float ox = objn[bl];

        if (am >= 0) {
            t_obj = focal1(ox);

            float ax1 = sx1[am], ay1 = sy1[am], ax2 = sx2[am], ay2 = sy2[am];
            float lt = fmaxf(lx - ax1, 1e-6f), tt = fmaxf(ly - ay1, 1e-6f);
            float rt = fmaxf(ax2 - lx, 1e-6f), bt = fmaxf(ay2 - ly, 1e-6f);

            float hor = __fdividef(fminf(lt, rt), fmaxf(fmaxf(lt, rt), 1e-6f));
            float ver = __fdividef(fminf(tt, bt), fmaxf(fmaxf(tt, bt), 1e-6f));
            float ctr_t = sqrtf(fmaxf(hor * ver, 0.0f));
            float wgt = fmaxf(ctr_t, 0.1f);
            t_w = wgt;

            float cxv = ctrn[bl];
            float spc; (void)sigmoid_sp(cxv, spc);
            t_ctr = (spc - cxv * ctr_t) * wgt;

            float4 bd = reinterpret_cast<const float4*>(deltas)[bl];
            float d0 = fabsf(bd.x - lt), d1 = fabsf(bd.y - tt);
            float d2 = fabsf(bd.z - rt), d3 = fabsf(bd.w - bt);
            float s0 = (d0 < 0.1f) ? 5.0f * d0 * d0 : d0 - 0.05f;
            float s1 = (d1 < 0.1f) ? 5.0f * d1 * d1 : d1 - 0.05f;
            float s2 = (d2 < 0.1f) ? 5.0f * d2 * d2 : d2 - 0.05f;
            float s3 = (d3 < 0.1f) ? 5.0f * d3 * d3 : d3 - 0.05f;
            t_l1 = 0.25f * (s0 + s1 + s2 + s3) * wgt;

            float4 pb = reinterpret_cast<const float4*>(boxes)[bl];
            float px1 = pb.x, py1 = pb.y, px2 = pb.z, py2 = pb.w;
            float ix1 = fmaxf(px1, ax1), iy1 = fmaxf(py1, ay1);
            float ix2 = fminf(px2, ax2), iy2 = fminf(py2, ay2);
            float inter = fmaxf(ix2 - ix1, 0.0f) * fmaxf(iy2 - iy1, 0.0f);
            float ap = fmaxf(px2 - px1, 0.0f) * fmaxf(py2 - py1, 0.0f);
            float ag = fmaxf(ax2 - ax1, 0.0f) * fmaxf(ay2 - ay1, 0.0f);
            float uni = ap + ag - inter;
            float iou = __fdividef(inter, fmaxf(uni, 1e-6f));
            float hx1 = fminf(px1, ax1), hy1 = fminf(py1, ay1);
            float hx2 = fmaxf(px2, ax2), hy2 = fmaxf(py2, ay2);
            float hull = fmaxf(hx2 - hx1, 0.0f) * fmaxf(hy2 - hy1, 0.0f);
            float giou = iou - __fdividef(hull - uni, fmaxf(hull, 1e-6f));
            t_giou = (1.0f - giou) * wgt;

            float xl = logits[(size_t)bl * C + slab[am]];
            t_cls = focal1(xl) - focal0(xl);
        } else {
            t_obj = focal0(ox);
        }
    }

    // ---- combined block reduction (one __syncthreads round) --------------
    {
        __shared__ float sh[6][8];
        int lane = threadIdx.x & 31, wid = threadIdx.x >> 5;
        float v0 = t_obj, v1 = t_cls, v2 = t_ctr, v3 = t_l1, v4 = t_giou, v5 = t_w;
#pragma unroll
        for (int o = 16; o; o >>= 1) {
            v0 += __shfl_down_sync(0xffffffffu, v0, o);
            v1 += __shfl_down_sync(0xffffffffu, v1, o);
            v2 += __shfl_down_sync(0xffffffffu, v2, o);
            v3 += __shfl_down_sync(0xffffffffu, v3, o);
            v4 += __shfl_down_sync(0xffffffffu, v4, o);
            v5 += __shfl_down_sync(0xffffffffu, v5, o);
        }
        if (lane == 0) {
            sh[0][wid] = v0; sh[1][wid] = v1; sh[2][wid] = v2;
            sh[3][wid] = v3; sh[4][wid] = v4; sh[5][wid] = v5;
        }
        __syncthreads();
        if (wid == 0 && lane < 6) {
            float s = 0.0f;
#pragma unroll
            for (int k = 0; k < 8; k++) s += sh[lane][k];
            atomicAdd(&g_acc[lane], (double)s);
        }
    }

    // ---- last block finalizes + resets globals for the next replay --------
    if (threadIdx.x == 0) {
        __threadfence();
        unsigned int total = gridDim.x * gridDim.y;
        unsigned int prev = atomicAdd(&g_done, 1u);
        if (prev == total - 1) {
            volatile double* acc = g_acc;
            double nBL  = (double)B * (double)L;
            double nBLC = nBL * (double)C;
            double wsum = acc[5];
            double inv_w = (wsum != 0.0) ? (1.0 / wsum) : 0.0;
            double loss = 1.0 * acc[0] / nBL
                        + 1.5 * acc[1] / nBLC
                        + 0.5 * acc[2] * inv_w
                        + 5.0 * acc[3] * inv_w
                        + 2.0 * acc[4] * inv_w;
            out[0] = (float)loss;
            // reset to module-load state for the next graph replay
            for (int k = 0; k < 8; k++) g_acc[k] = 0.0;
            g_done = 0u;
            g_ok = 1;
            __threadfence();
        }
    }
}

// ---------------- launch ---------------------------------------------------

extern "C" void kernel_launch(void* const* d_in, const int* in_sizes, int n_in,
                              void* d_out, int out_size)
{
    const float* boxes  = (const float*)d_in[0];
    const float* deltas = (const float*)d_in[1];
    const float* logits = (const float*)d_in[2];
    const float* objn   = (const float*)d_in[3];
    const float* ctrn   = (const float*)d_in[4];
    const float* loc    = (const float*)d_in[5];
    const float* gtb    = (const float*)d_in[6];
    const int*   gtl    = (const int*)d_in[7];
    const int*   ghp    = (n_in > 8) ? (const int*)d_in[8] : nullptr;
    const int*   gwp    = (n_in > 9) ? (const int*)d_in[9] : nullptr;

    int L = in_sizes[5] / 2;
    int B = in_sizes[3] / L;
    int M = in_sizes[7] / B;
    int C = in_sizes[2] / in_sizes[3];

    k_bulk<<<2368, 256>>>(logits, (long long)in_sizes[2], loc, ghp, gwp, L);
    dim3 gloc((L + 255) / 256, B);
    k_loc<<<gloc, 256>>>(boxes, deltas, logits, objn, ctrn, loc, gtb, gtl,
                         ghp, gwp, B, M, L, C, (float*)d_out);
}